// round 7
// baseline (speedup 1.0000x reference)
#include <cuda_runtime.h>
#include <math.h>

#define H     2048
#define T     4096
#define G3    (3 * H)
#define K_IN  2048
#define NBMAX 160

// ---------------- device scratch / flag state ----------------
__device__ float    g_ig[(size_t)T * G3];      // igates [T][3H]
__device__ unsigned g_flags[NBMAX * 8];        // per-CTA epoch flags, 32B stride

// =================================================================
// Kernel 1: igates = xs @ Wi^T + bi    (fp32 SMEM-tiled GEMM)
// =================================================================
#define BM 128
#define BN 128
#define BK 16

__global__ __launch_bounds__(256, 2)
void igates_gemm(const float* __restrict__ A,
                 const float* __restrict__ B,
                 const float* __restrict__ bi)
{
    __shared__ float As[BK][BM + 4];
    __shared__ float Bs[BK][BN + 4];

    const int tid = threadIdx.x;
    const int m0  = blockIdx.y * BM;
    const int n0  = blockIdx.x * BN;
    const int tx  = tid & 15;
    const int ty  = tid >> 4;

    float acc[8][8];
#pragma unroll
    for (int i = 0; i < 8; i++)
#pragma unroll
        for (int j = 0; j < 8; j++) acc[i][j] = 0.f;

    for (int k0 = 0; k0 < K_IN; k0 += BK) {
#pragma unroll
        for (int p = 0; p < 2; p++) {
            int f   = tid + p * 256;
            int row = f >> 2;
            int c4  = (f & 3) * 4;
            float4 va = *reinterpret_cast<const float4*>(
                &A[(size_t)(m0 + row) * K_IN + k0 + c4]);
            As[c4 + 0][row] = va.x; As[c4 + 1][row] = va.y;
            As[c4 + 2][row] = va.z; As[c4 + 3][row] = va.w;
            float4 vb = *reinterpret_cast<const float4*>(
                &B[(size_t)(n0 + row) * K_IN + k0 + c4]);
            Bs[c4 + 0][row] = vb.x; Bs[c4 + 1][row] = vb.y;
            Bs[c4 + 2][row] = vb.z; Bs[c4 + 3][row] = vb.w;
        }
        __syncthreads();

#pragma unroll
        for (int kk = 0; kk < BK; kk++) {
            float a[8], b[8];
            *reinterpret_cast<float4*>(&a[0]) = *reinterpret_cast<float4*>(&As[kk][ty * 8]);
            *reinterpret_cast<float4*>(&a[4]) = *reinterpret_cast<float4*>(&As[kk][ty * 8 + 4]);
            *reinterpret_cast<float4*>(&b[0]) = *reinterpret_cast<float4*>(&Bs[kk][tx * 8]);
            *reinterpret_cast<float4*>(&b[4]) = *reinterpret_cast<float4*>(&Bs[kk][tx * 8 + 4]);
#pragma unroll
            for (int i = 0; i < 8; i++)
#pragma unroll
                for (int j = 0; j < 8; j++)
                    acc[i][j] = fmaf(a[i], b[j], acc[i][j]);
        }
        __syncthreads();
    }

#pragma unroll
    for (int i = 0; i < 8; i++) {
        int m = m0 + ty * 8 + i;
#pragma unroll
        for (int j = 0; j < 8; j += 4) {
            int n = n0 + tx * 8 + j;
            float4 v;
            v.x = acc[i][j + 0] + bi[n + 0];
            v.y = acc[i][j + 1] + bi[n + 1];
            v.z = acc[i][j + 2] + bi[n + 2];
            v.w = acc[i][j + 3] + bi[n + 3];
            *reinterpret_cast<float4*>(&g_ig[(size_t)m * G3 + n]) = v;
        }
    }
}

// ---------------- release / acquire helpers ----------------
__device__ __forceinline__ void flag_release(unsigned* p, unsigned v) {
    asm volatile("st.release.gpu.global.u32 [%0], %1;" :: "l"(p), "r"(v) : "memory");
}
__device__ __forceinline__ unsigned flag_acquire(const unsigned* p) {
    unsigned v;
    asm volatile("ld.acquire.gpu.global.u32 %0, [%1];" : "=r"(v) : "l"(p) : "memory");
    return v;
}
__device__ __forceinline__ void flag_wait(const unsigned* p, unsigned tgt) {
#pragma unroll 1
    while ((int)(flag_acquire(p) - tgt) < 0) { }
}

// =================================================================
// Kernel 2: persistent GRU scan with POINT-TO-POINT dataflow sync.
//   148 CTAs x 256 threads, 1 CTA/SM. No grid barrier: each thread
//   waits only on the flags of the CTAs owning the h-chunks it loads.
//   h lives at a fresh address every step (out[t]), so flags are
//   monotone epochs and CTAs may drift freely (wavefront pipeline).
// =================================================================
#define NSR_MAX 26
#define SCAN_SMEM ((NSR_MAX * H + H + 64) * 4)   // 221,440 bytes

__global__ __launch_bounds__(256, 1)
void gru_scan(const float* __restrict__ Wh,
              const float* __restrict__ init_state,
              const float* __restrict__ bn,
              float* __restrict__ out)
{
    extern __shared__ float smem[];
    const int NB   = gridDim.x;
    const int cta  = blockIdx.x;
    const int tid  = threadIdx.x;
    const int lane = tid & 31;
    const int warp = tid >> 5;          // 0..7

    const int chunk = (H + NB - 1) / NB;
    const int j0    = cta * chunk;
    int nj = H - j0;
    if (nj > chunk) nj = chunk;
    if (nj < 0) nj = 0;
    const int nrows = 3 * nj;

    float* sw    = smem;                 // NSR_MAX rows x 2048 (rows 16..41)
    float* sh    = smem + NSR_MAX * H;   // staged h (2048)
    float* sdots = sh + H;               // 48 dot results
    float4* sh4  = reinterpret_cast<float4*>(sh);

    // epoch base: own flag (written only by this CTA; all equal at launch)
    const unsigned epoch = g_flags[cta * 8];

    // ---- preload SMEM-resident weight rows (rr = 16..nrows-1), once ----
    const int nsr = (nrows > 16) ? (nrows - 16) : 0;   // <= 26
    for (int idx = tid; idx < nsr * (H / 4); idx += 256) {
        int r  = idx >> 9;
        int c  = idx & 511;
        int rr = 16 + r;
        int g  = rr / nj;
        int jj = rr - g * nj;
        reinterpret_cast<float4*>(sw)[r * (H / 4) + c] =
            reinterpret_cast<const float4*>(Wh + (size_t)(g * H + j0 + jj) * H)[c];
    }

    // ---- per-warp row slots ----
    const int rr0 = warp,      rr1 = warp + 8,  rr2 = warp + 16;
    const int rr3 = warp + 24, rr4 = warp + 32, rr5 = warp + 40;
    const bool v0 = rr0 < nrows, v1 = rr1 < nrows, v2 = rr2 < nrows;
    const bool v3 = rr3 < nrows, v4 = rr4 < nrows, v5 = rr5 < nrows;

    // ---- register-resident weights for slots 0,1 ----
    float4 wreg0[16], wreg1[16];
    {
        const float* row;
        int g, jj;
        g = v0 ? (rr0 / nj) : 0; jj = v0 ? (rr0 - g * nj) : 0;
        row = Wh + (size_t)(g * H + j0 + jj) * H;
#pragma unroll
        for (int i = 0; i < 16; i++)
            wreg0[i] = reinterpret_cast<const float4*>(row)[lane + 32 * i];
        g = v1 ? (rr1 / nj) : 0; jj = v1 ? (rr1 - g * nj) : 0;
        row = Wh + (size_t)(g * H + j0 + jj) * H;
#pragma unroll
        for (int i = 0; i < 16; i++)
            wreg1[i] = reinterpret_cast<const float4*>(row)[lane + 32 * i];
    }

    const float4* p2 = reinterpret_cast<const float4*>(v2 ? (sw + (rr2 - 16) * H) : sw);
    const float4* p3 = reinterpret_cast<const float4*>(v3 ? (sw + (rr3 - 16) * H) : sw);
    const float4* p4 = reinterpret_cast<const float4*>(v4 ? (sw + (rr4 - 16) * H) : sw);
    const float4* p5 = reinterpret_cast<const float4*>(v5 ? (sw + (rr5 - 16) * H) : sw);

    const bool doPoint = (tid < nj);
    const int  myj     = j0 + (doPoint ? tid : 0);
    const float mybn   = doPoint ? bn[myj] : 0.f;

    // ---- owners of this thread's two h float4 loads (f = tid, tid+256) ----
    // float4 f covers floats 4f..4f+3; owner(j) = j / chunk (< NB).
    int oa = (4 * tid) / chunk;            if (oa > NB - 1) oa = NB - 1;
    int ob = (4 * tid + 3) / chunk;        if (ob > NB - 1) ob = NB - 1;
    int oc = (4 * (tid + 256)) / chunk;    if (oc > NB - 1) oc = NB - 1;
    int od = (4 * (tid + 256) + 3) / chunk;if (od > NB - 1) od = NB - 1;
    const bool wa = (oa != cta);
    const bool wb = (ob != oa) && (ob != cta);
    const bool wc = (oc != cta);
    const bool wd = (od != oc) && (od != cta);

    // prefetch igates for t = 0
    float gr = 0.f, gz = 0.f, gnv = 0.f;
    if (doPoint) {
        gr  = g_ig[myj];
        gz  = g_ig[H + myj];
        gnv = g_ig[2 * H + myj];
    }

    __syncthreads();   // SMEM weights ready

#pragma unroll 1
    for (int t = 0; t < T; t++) {
        // ---- wait producers of my h pieces, then stage into SMEM ----
        const float* hsrc;
        if (t == 0) {
            hsrc = init_state;
        } else {
            hsrc = out + (size_t)(t - 1) * H;
            const unsigned tgt = epoch + (unsigned)t;
            if (wa) flag_wait(&g_flags[oa * 8], tgt);
            if (wb) flag_wait(&g_flags[ob * 8], tgt);
            if (wc) flag_wait(&g_flags[oc * 8], tgt);
            if (wd) flag_wait(&g_flags[od * 8], tgt);
        }
        sh4[tid]       = reinterpret_cast<const float4*>(hsrc)[tid];
        sh4[tid + 256] = reinterpret_cast<const float4*>(hsrc)[tid + 256];
        __syncthreads();

        // ---- six dot products per warp ----
        float a0 = 0.f, a1 = 0.f, a2 = 0.f, a3 = 0.f, a4 = 0.f, a5 = 0.f;
#pragma unroll
        for (int i = 0; i < 16; i++) {
            const int k = lane + 32 * i;
            const float4 hv = sh4[k];
            a0 = fmaf(wreg0[i].x, hv.x, a0); a0 = fmaf(wreg0[i].y, hv.y, a0);
            a0 = fmaf(wreg0[i].z, hv.z, a0); a0 = fmaf(wreg0[i].w, hv.w, a0);
            a1 = fmaf(wreg1[i].x, hv.x, a1); a1 = fmaf(wreg1[i].y, hv.y, a1);
            a1 = fmaf(wreg1[i].z, hv.z, a1); a1 = fmaf(wreg1[i].w, hv.w, a1);
            if (v2) { float4 w = p2[k];
                a2 = fmaf(w.x, hv.x, a2); a2 = fmaf(w.y, hv.y, a2);
                a2 = fmaf(w.z, hv.z, a2); a2 = fmaf(w.w, hv.w, a2); }
            if (v3) { float4 w = p3[k];
                a3 = fmaf(w.x, hv.x, a3); a3 = fmaf(w.y, hv.y, a3);
                a3 = fmaf(w.z, hv.z, a3); a3 = fmaf(w.w, hv.w, a3); }
            if (v4) { float4 w = p4[k];
                a4 = fmaf(w.x, hv.x, a4); a4 = fmaf(w.y, hv.y, a4);
                a4 = fmaf(w.z, hv.z, a4); a4 = fmaf(w.w, hv.w, a4); }
            if (v5) { float4 w = p5[k];
                a5 = fmaf(w.x, hv.x, a5); a5 = fmaf(w.y, hv.y, a5);
                a5 = fmaf(w.z, hv.z, a5); a5 = fmaf(w.w, hv.w, a5); }
        }
#pragma unroll
        for (int off = 16; off; off >>= 1) {
            a0 += __shfl_xor_sync(0xffffffffu, a0, off);
            a1 += __shfl_xor_sync(0xffffffffu, a1, off);
            a2 += __shfl_xor_sync(0xffffffffu, a2, off);
            a3 += __shfl_xor_sync(0xffffffffu, a3, off);
            a4 += __shfl_xor_sync(0xffffffffu, a4, off);
            a5 += __shfl_xor_sync(0xffffffffu, a5, off);
        }
        if (lane == 0) {
            if (v0) sdots[rr0] = a0;
            if (v1) sdots[rr1] = a1;
            if (v2) sdots[rr2] = a2;
            if (v3) sdots[rr3] = a3;
            if (v4) sdots[rr4] = a4;
            if (v5) sdots[rr5] = a5;
        }
        __syncthreads();

        // ---- pointwise GRU update (fast transcendentals) ----
        if (doPoint) {
            float hr = sdots[tid];
            float hz = sdots[nj + tid];
            float hn = sdots[2 * nj + tid];
            float r  = __fdividef(1.f, 1.f + __expf(-(gr + hr)));
            float u  = __fdividef(1.f, 1.f + __expf(-(gz + hz)));
            float x  = gnv + r * (hn + mybn);
            float nv = __fdividef(2.f, 1.f + __expf(-2.f * x)) - 1.f;  // tanh
            float hprev = sh[myj];
            float hnext = (1.f - u) * nv + u * hprev;
            out[(size_t)t * H + myj] = hnext;
            if (t == T - 1) out[(size_t)T * H + myj] = hnext;  // last_state
        }

        // ---- publish: fence stores, then post own flag ----
        __threadfence();          // storers drain h to gpu scope
        __syncthreads();          // all storers fenced
        if (tid == 0)
            flag_release(&g_flags[cta * 8], epoch + (unsigned)(t + 1));

        // overlap: issue next step's igate loads now (in flight during
        // the next iteration's flag waits)
        if (doPoint && (t + 1) < T) {
            const float* igt = g_ig + (size_t)(t + 1) * G3;
            gr  = igt[myj];
            gz  = igt[H + myj];
            gnv = igt[2 * H + myj];
        }
    }
}

// =================================================================
// launch
// =================================================================
extern "C" void kernel_launch(void* const* d_in, const int* in_sizes, int n_in,
                              void* d_out, int out_size)
{
    const float* xs         = (const float*)d_in[0];  // [4096,2048]
    const float* init_state = (const float*)d_in[1];  // [2048]
    const float* Wi         = (const float*)d_in[2];  // [6144,2048]
    const float* Wh         = (const float*)d_in[3];  // [6144,2048]
    const float* bi         = (const float*)d_in[4];  // [6144]
    const float* bn         = (const float*)d_in[5];  // [2048]
    float* out              = (float*)d_out;          // [4096*2048 + 2048]

    (void)in_sizes; (void)n_in; (void)out_size;

    // 1) input-gate GEMM: grid (N/BN, M/BM) = (48, 32)
    igates_gemm<<<dim3(G3 / BN, T / BM), 256>>>(xs, Wi, bi);

    // 2) persistent scan: one CTA per SM
    int dev = 0;
    cudaGetDevice(&dev);
    int nsm = 148;
    cudaDeviceGetAttribute(&nsm, cudaDevAttrMultiProcessorCount, dev);
    if (nsm < 1) nsm = 148;
    if (nsm > NBMAX) nsm = NBMAX;

    cudaFuncSetAttribute(gru_scan, cudaFuncAttributeMaxDynamicSharedMemorySize, SCAN_SMEM);
    gru_scan<<<nsm, 256, SCAN_SMEM>>>(Wh, init_state, bn, out);
}

// round 8
// speedup vs baseline: 1.1411x; 1.1411x over previous
#include <cuda_runtime.h>
#include <math.h>

#define H     2048
#define T     4096
#define G3    (3 * H)
#define K_IN  2048
#define NBMAX 160
#define LINEF 32          // floats per mailbox line (128 B)

// ---------------- device scratch / mailbox state ----------------
__device__ float    g_ig[(size_t)T * G3];              // igates [T][3H]
__device__ float    g_hx[(size_t)T * NBMAX * LINEF];   // per-step h mailboxes (~84 MB)
__device__ unsigned g_epochs[NBMAX * 8];               // per-CTA launch epoch counters

// =================================================================
// Kernel 1: igates = xs @ Wi^T + bi    (fp32 SMEM-tiled GEMM)
// =================================================================
#define BM 128
#define BN 128
#define BK 16

__global__ __launch_bounds__(256, 2)
void igates_gemm(const float* __restrict__ A,
                 const float* __restrict__ B,
                 const float* __restrict__ bi)
{
    __shared__ float As[BK][BM + 4];
    __shared__ float Bs[BK][BN + 4];

    const int tid = threadIdx.x;
    const int m0  = blockIdx.y * BM;
    const int n0  = blockIdx.x * BN;
    const int tx  = tid & 15;
    const int ty  = tid >> 4;

    float acc[8][8];
#pragma unroll
    for (int i = 0; i < 8; i++)
#pragma unroll
        for (int j = 0; j < 8; j++) acc[i][j] = 0.f;

    for (int k0 = 0; k0 < K_IN; k0 += BK) {
#pragma unroll
        for (int p = 0; p < 2; p++) {
            int f   = tid + p * 256;
            int row = f >> 2;
            int c4  = (f & 3) * 4;
            float4 va = *reinterpret_cast<const float4*>(
                &A[(size_t)(m0 + row) * K_IN + k0 + c4]);
            As[c4 + 0][row] = va.x; As[c4 + 1][row] = va.y;
            As[c4 + 2][row] = va.z; As[c4 + 3][row] = va.w;
            float4 vb = *reinterpret_cast<const float4*>(
                &B[(size_t)(n0 + row) * K_IN + k0 + c4]);
            Bs[c4 + 0][row] = vb.x; Bs[c4 + 1][row] = vb.y;
            Bs[c4 + 2][row] = vb.z; Bs[c4 + 3][row] = vb.w;
        }
        __syncthreads();

#pragma unroll
        for (int kk = 0; kk < BK; kk++) {
            float a[8], b[8];
            *reinterpret_cast<float4*>(&a[0]) = *reinterpret_cast<float4*>(&As[kk][ty * 8]);
            *reinterpret_cast<float4*>(&a[4]) = *reinterpret_cast<float4*>(&As[kk][ty * 8 + 4]);
            *reinterpret_cast<float4*>(&b[0]) = *reinterpret_cast<float4*>(&Bs[kk][tx * 8]);
            *reinterpret_cast<float4*>(&b[4]) = *reinterpret_cast<float4*>(&Bs[kk][tx * 8 + 4]);
#pragma unroll
            for (int i = 0; i < 8; i++)
#pragma unroll
                for (int j = 0; j < 8; j++)
                    acc[i][j] = fmaf(a[i], b[j], acc[i][j]);
        }
        __syncthreads();
    }

#pragma unroll
    for (int i = 0; i < 8; i++) {
        int m = m0 + ty * 8 + i;
#pragma unroll
        for (int j = 0; j < 8; j += 4) {
            int n = n0 + tx * 8 + j;
            float4 v;
            v.x = acc[i][j + 0] + bi[n + 0];
            v.y = acc[i][j + 1] + bi[n + 1];
            v.z = acc[i][j + 2] + bi[n + 2];
            v.w = acc[i][j + 3] + bi[n + 3];
            *reinterpret_cast<float4*>(&g_ig[(size_t)m * G3 + n]) = v;
        }
    }
}

// ---------------- release / acquire helpers ----------------
__device__ __forceinline__ void flag_release(unsigned* p, unsigned v) {
    asm volatile("st.release.gpu.global.u32 [%0], %1;" :: "l"(p), "r"(v) : "memory");
}
__device__ __forceinline__ unsigned flag_acquire(const unsigned* p) {
    unsigned v;
    asm volatile("ld.acquire.gpu.global.u32 %0, [%1];" : "=r"(v) : "l"(p) : "memory");
    return v;
}
__device__ __forceinline__ void flag_wait(const unsigned* p, unsigned tgt) {
#pragma unroll 1
    while ((int)(flag_acquire(p) - tgt) < 0) { }
}

// =================================================================
// Kernel 2: persistent GRU scan with MAILBOX h-exchange.
//   148 CTAs x 256 threads, 1 CTA/SM.
//   Per step, CTA c writes its <=14 h values + tag into ONE 128B line
//   g_hx[t][c]; consumers poll the tag and pull the payload from the
//   same line (one L2 round trip, no grid barrier, no threadfence).
//   Weights fully resident: 16 rows in registers + 26 rows in SMEM.
// =================================================================
#define NSR_MAX 26
#define SCAN_SMEM ((NSR_MAX * H + H + 64) * 4)   // 221,440 bytes

__global__ __launch_bounds__(256, 1)
void gru_scan(const float* __restrict__ Wh,
              const float* __restrict__ init_state,
              const float* __restrict__ bn,
              float* __restrict__ out)
{
    extern __shared__ float smem[];
    const int NB   = gridDim.x;
    const int cta  = blockIdx.x;
    const int tid  = threadIdx.x;
    const int lane = tid & 31;
    const int warp = tid >> 5;          // 0..7

    const int chunk = (H + NB - 1) / NB;     // <= 30 guaranteed (NB >= 69)
    const int j0    = cta * chunk;
    int nj = H - j0;
    if (nj > chunk) nj = chunk;
    if (nj < 0) nj = 0;
    const int nrows = 3 * nj;

    float* sw    = smem;                 // NSR_MAX rows x 2048 (rows 16..41)
    float* sh    = smem + NSR_MAX * H;   // staged h (2048)
    float* sdots = sh + H;               // 48 dot results
    float4* sh4  = reinterpret_cast<float4*>(sh);

    // per-launch epoch (own counter; all CTAs equal at launch start)
    const unsigned epoch = g_epochs[cta * 8];

    // ---- preload SMEM-resident weight rows (rr = 16..nrows-1), once ----
    const int nsr = (nrows > 16) ? (nrows - 16) : 0;   // <= 26
    for (int idx = tid; idx < nsr * (H / 4); idx += 256) {
        int r  = idx >> 9;
        int c  = idx & 511;
        int rr = 16 + r;
        int g  = rr / nj;
        int jj = rr - g * nj;
        reinterpret_cast<float4*>(sw)[r * (H / 4) + c] =
            reinterpret_cast<const float4*>(Wh + (size_t)(g * H + j0 + jj) * H)[c];
    }

    // ---- per-warp row slots ----
    const int rr0 = warp,      rr1 = warp + 8,  rr2 = warp + 16;
    const int rr3 = warp + 24, rr4 = warp + 32, rr5 = warp + 40;
    const bool v0 = rr0 < nrows, v1 = rr1 < nrows, v2 = rr2 < nrows;
    const bool v3 = rr3 < nrows, v4 = rr4 < nrows, v5 = rr5 < nrows;

    // ---- register-resident weights for slots 0,1 ----
    float4 wreg0[16], wreg1[16];
    {
        const float* row;
        int g, jj;
        g = v0 ? (rr0 / nj) : 0; jj = v0 ? (rr0 - g * nj) : 0;
        row = Wh + (size_t)(g * H + j0 + jj) * H;
#pragma unroll
        for (int i = 0; i < 16; i++)
            wreg0[i] = reinterpret_cast<const float4*>(row)[lane + 32 * i];
        g = v1 ? (rr1 / nj) : 0; jj = v1 ? (rr1 - g * nj) : 0;
        row = Wh + (size_t)(g * H + j0 + jj) * H;
#pragma unroll
        for (int i = 0; i < 16; i++)
            wreg1[i] = reinterpret_cast<const float4*>(row)[lane + 32 * i];
    }

    const float4* p2 = reinterpret_cast<const float4*>(v2 ? (sw + (rr2 - 16) * H) : sw);
    const float4* p3 = reinterpret_cast<const float4*>(v3 ? (sw + (rr3 - 16) * H) : sw);
    const float4* p4 = reinterpret_cast<const float4*>(v4 ? (sw + (rr4 - 16) * H) : sw);
    const float4* p5 = reinterpret_cast<const float4*>(v5 ? (sw + (rr5 - 16) * H) : sw);

    const bool doPoint = (tid < nj);
    const int  myj     = j0 + (doPoint ? tid : 0);
    const float mybn   = doPoint ? bn[myj] : 0.f;

    // consumer role: thread i < NB pulls mailbox line i
    const int  mline = tid;
    int mcnt = 0, mbase = 0;
    if (tid < NB) {
        mbase = mline * chunk;
        mcnt  = H - mbase;
        if (mcnt > chunk) mcnt = chunk;
        if (mcnt < 0) mcnt = 0;
    }

    // prefetch igates for t = 0
    float gr = 0.f, gz = 0.f, gnv = 0.f;
    if (doPoint) {
        gr  = g_ig[myj];
        gz  = g_ig[H + myj];
        gnv = g_ig[2 * H + myj];
    }

    __syncthreads();   // SMEM weights ready

#pragma unroll 1
    for (int t = 0; t < T; t++) {
        // ---- acquire h_{t-1}: pull mailboxes (or init_state at t=0) ----
        if (t == 0) {
            sh4[tid]       = reinterpret_cast<const float4*>(init_state)[tid];
            sh4[tid + 256] = reinterpret_cast<const float4*>(init_state)[tid + 256];
        } else if (mcnt > 0) {
            const float* line = g_hx + ((size_t)(t - 1) * NBMAX + mline) * LINEF;
            flag_wait(reinterpret_cast<const unsigned*>(line + LINEF - 1),
                      epoch + (unsigned)t);
            const int nr = (mcnt + 3) >> 2;
#pragma unroll 1
            for (int r = 0; r < nr; r++) {
                float4 d = __ldcg(reinterpret_cast<const float4*>(line) + r);
                int b = 4 * r;
                if (b + 0 < mcnt) sh[mbase + b + 0] = d.x;
                if (b + 1 < mcnt) sh[mbase + b + 1] = d.y;
                if (b + 2 < mcnt) sh[mbase + b + 2] = d.z;
                if (b + 3 < mcnt) sh[mbase + b + 3] = d.w;
            }
        }
        __syncthreads();

        // ---- six dot products per warp ----
        float a0 = 0.f, a1 = 0.f, a2 = 0.f, a3 = 0.f, a4 = 0.f, a5 = 0.f;
#pragma unroll
        for (int i = 0; i < 16; i++) {
            const int k = lane + 32 * i;
            const float4 hv = sh4[k];
            a0 = fmaf(wreg0[i].x, hv.x, a0); a0 = fmaf(wreg0[i].y, hv.y, a0);
            a0 = fmaf(wreg0[i].z, hv.z, a0); a0 = fmaf(wreg0[i].w, hv.w, a0);
            a1 = fmaf(wreg1[i].x, hv.x, a1); a1 = fmaf(wreg1[i].y, hv.y, a1);
            a1 = fmaf(wreg1[i].z, hv.z, a1); a1 = fmaf(wreg1[i].w, hv.w, a1);
            if (v2) { float4 w = p2[k];
                a2 = fmaf(w.x, hv.x, a2); a2 = fmaf(w.y, hv.y, a2);
                a2 = fmaf(w.z, hv.z, a2); a2 = fmaf(w.w, hv.w, a2); }
            if (v3) { float4 w = p3[k];
                a3 = fmaf(w.x, hv.x, a3); a3 = fmaf(w.y, hv.y, a3);
                a3 = fmaf(w.z, hv.z, a3); a3 = fmaf(w.w, hv.w, a3); }
            if (v4) { float4 w = p4[k];
                a4 = fmaf(w.x, hv.x, a4); a4 = fmaf(w.y, hv.y, a4);
                a4 = fmaf(w.z, hv.z, a4); a4 = fmaf(w.w, hv.w, a4); }
            if (v5) { float4 w = p5[k];
                a5 = fmaf(w.x, hv.x, a5); a5 = fmaf(w.y, hv.y, a5);
                a5 = fmaf(w.z, hv.z, a5); a5 = fmaf(w.w, hv.w, a5); }
        }
#pragma unroll
        for (int off = 16; off; off >>= 1) {
            a0 += __shfl_xor_sync(0xffffffffu, a0, off);
            a1 += __shfl_xor_sync(0xffffffffu, a1, off);
            a2 += __shfl_xor_sync(0xffffffffu, a2, off);
            a3 += __shfl_xor_sync(0xffffffffu, a3, off);
            a4 += __shfl_xor_sync(0xffffffffu, a4, off);
            a5 += __shfl_xor_sync(0xffffffffu, a5, off);
        }
        if (lane == 0) {
            if (v0) sdots[rr0] = a0;
            if (v1) sdots[rr1] = a1;
            if (v2) sdots[rr2] = a2;
            if (v3) sdots[rr3] = a3;
            if (v4) sdots[rr4] = a4;
            if (v5) sdots[rr5] = a5;
        }
        __syncthreads();

        // ---- pointwise GRU update + mailbox data store ----
        if (doPoint) {
            float hr = sdots[tid];
            float hz = sdots[nj + tid];
            float hn = sdots[2 * nj + tid];
            float r  = __fdividef(1.f, 1.f + __expf(-(gr + hr)));
            float u  = __fdividef(1.f, 1.f + __expf(-(gz + hz)));
            float x  = gnv + r * (hn + mybn);
            float nv = __fdividef(2.f, 1.f + __expf(-2.f * x)) - 1.f;  // tanh
            float hprev = sh[myj];
            float hnext = (1.f - u) * nv + u * hprev;
            out[(size_t)t * H + myj] = hnext;                      // output
            g_hx[((size_t)t * NBMAX + cta) * LINEF + tid] = hnext; // mailbox
            if (t == T - 1) out[(size_t)T * H + myj] = hnext;      // last_state
        }

        // ---- publish: barrier orders peers' stores, release posts tag ----
        __syncthreads();
        if (tid == 0) {
            unsigned* tagp = reinterpret_cast<unsigned*>(
                g_hx + ((size_t)t * NBMAX + cta) * LINEF + (LINEF - 1));
            flag_release(tagp, epoch + (unsigned)(t + 1));
        }

        // overlap: next step's igate loads fly during upcoming mailbox polls
        if (doPoint && (t + 1) < T) {
            const float* igt = g_ig + (size_t)(t + 1) * G3;
            gr  = igt[myj];
            gz  = igt[H + myj];
            gnv = igt[2 * H + myj];
        }
    }

    // bump own epoch for next launch / graph replay
    if (tid == 0)
        g_epochs[cta * 8] = epoch + (unsigned)T;
}

// =================================================================
// launch
// =================================================================
extern "C" void kernel_launch(void* const* d_in, const int* in_sizes, int n_in,
                              void* d_out, int out_size)
{
    const float* xs         = (const float*)d_in[0];  // [4096,2048]
    const float* init_state = (const float*)d_in[1];  // [2048]
    const float* Wi         = (const float*)d_in[2];  // [6144,2048]
    const float* Wh         = (const float*)d_in[3];  // [6144,2048]
    const float* bi         = (const float*)d_in[4];  // [6144]
    const float* bn         = (const float*)d_in[5];  // [2048]
    float* out              = (float*)d_out;          // [4096*2048 + 2048]

    (void)in_sizes; (void)n_in; (void)out_size;

    // 1) input-gate GEMM: grid (N/BN, M/BM) = (48, 32)
    igates_gemm<<<dim3(G3 / BN, T / BM), 256>>>(xs, Wi, bi);

    // 2) persistent scan: one CTA per SM
    int dev = 0;
    cudaGetDevice(&dev);
    int nsm = 148;
    cudaDeviceGetAttribute(&nsm, cudaDevAttrMultiProcessorCount, dev);
    if (nsm < 1) nsm = 148;
    if (nsm > NBMAX) nsm = NBMAX;

    cudaFuncSetAttribute(gru_scan, cudaFuncAttributeMaxDynamicSharedMemorySize, SCAN_SMEM);
    gru_scan<<<nsm, 256, SCAN_SMEM>>>(Wh, init_state, bn, out);
}

// round 9
// speedup vs baseline: 1.4935x; 1.3088x over previous
#include <cuda_runtime.h>
#include <math.h>

#define H     2048
#define T     4096
#define G3    (3 * H)
#define K_IN  2048
#define NBMAX 160

// ---------------- device scratch / flag state ----------------
__device__ float    g_ig[(size_t)T * G3];      // igates [T][3H]
__device__ unsigned g_flags[NBMAX * 8];        // per-CTA epoch flags, 32B stride

// =================================================================
// Kernel 1: igates = xs @ Wi^T + bi
//   fp32 SMEM-tiled GEMM, 2-stage software pipeline (double buffer):
//   LDG for tile k+1 in flight while computing tile k from SMEM.
// =================================================================
#define BM 128
#define BN 128
#define BK 16

__global__ __launch_bounds__(256, 2)
void igates_gemm(const float* __restrict__ A,
                 const float* __restrict__ B,
                 const float* __restrict__ bi)
{
    __shared__ float As[2][BK][BM + 4];
    __shared__ float Bs[2][BK][BN + 4];

    const int tid = threadIdx.x;
    const int m0  = blockIdx.y * BM;
    const int n0  = blockIdx.x * BN;
    const int tx  = tid & 15;
    const int ty  = tid >> 4;

    // stage-load indexing: thread covers 2 float4 of A and 2 of B
    const int r0 = tid >> 1;               // 0..127  (row for fragment 0)
    const int c0 = (tid & 1) * 8;          // 0 or 8  (k-col base, 2 float4)

    float acc[8][8];
#pragma unroll
    for (int i = 0; i < 8; i++)
#pragma unroll
        for (int j = 0; j < 8; j++) acc[i][j] = 0.f;

    // ---- prologue: fetch k0 = 0 tiles into registers ----
    float4 ra0, ra1, rb0, rb1;
    ra0 = *reinterpret_cast<const float4*>(&A[(size_t)(m0 + r0) * K_IN + c0]);
    ra1 = *reinterpret_cast<const float4*>(&A[(size_t)(m0 + r0) * K_IN + c0 + 4]);
    rb0 = *reinterpret_cast<const float4*>(&B[(size_t)(n0 + r0) * K_IN + c0]);
    rb1 = *reinterpret_cast<const float4*>(&B[(size_t)(n0 + r0) * K_IN + c0 + 4]);

    int buf = 0;
    for (int k0 = 0; k0 < K_IN; k0 += BK) {
        // ---- store staged tile (transposed K-major) into buffer 'buf' ----
        As[buf][c0 + 0][r0] = ra0.x; As[buf][c0 + 1][r0] = ra0.y;
        As[buf][c0 + 2][r0] = ra0.z; As[buf][c0 + 3][r0] = ra0.w;
        As[buf][c0 + 4][r0] = ra1.x; As[buf][c0 + 5][r0] = ra1.y;
        As[buf][c0 + 6][r0] = ra1.z; As[buf][c0 + 7][r0] = ra1.w;
        Bs[buf][c0 + 0][r0] = rb0.x; Bs[buf][c0 + 1][r0] = rb0.y;
        Bs[buf][c0 + 2][r0] = rb0.z; Bs[buf][c0 + 3][r0] = rb0.w;
        Bs[buf][c0 + 4][r0] = rb1.x; Bs[buf][c0 + 5][r0] = rb1.y;
        Bs[buf][c0 + 6][r0] = rb1.z; Bs[buf][c0 + 7][r0] = rb1.w;
        __syncthreads();

        // ---- prefetch next tile (latency hidden under compute) ----
        if (k0 + BK < K_IN) {
            const int kn = k0 + BK;
            ra0 = *reinterpret_cast<const float4*>(&A[(size_t)(m0 + r0) * K_IN + kn + c0]);
            ra1 = *reinterpret_cast<const float4*>(&A[(size_t)(m0 + r0) * K_IN + kn + c0 + 4]);
            rb0 = *reinterpret_cast<const float4*>(&B[(size_t)(n0 + r0) * K_IN + kn + c0]);
            rb1 = *reinterpret_cast<const float4*>(&B[(size_t)(n0 + r0) * K_IN + kn + c0 + 4]);
        }

        // ---- compute from buffer 'buf' ----
#pragma unroll
        for (int kk = 0; kk < BK; kk++) {
            float a[8], b[8];
            *reinterpret_cast<float4*>(&a[0]) = *reinterpret_cast<float4*>(&As[buf][kk][ty * 8]);
            *reinterpret_cast<float4*>(&a[4]) = *reinterpret_cast<float4*>(&As[buf][kk][ty * 8 + 4]);
            *reinterpret_cast<float4*>(&b[0]) = *reinterpret_cast<float4*>(&Bs[buf][kk][tx * 8]);
            *reinterpret_cast<float4*>(&b[4]) = *reinterpret_cast<float4*>(&Bs[buf][kk][tx * 8 + 4]);
#pragma unroll
            for (int i = 0; i < 8; i++)
#pragma unroll
                for (int j = 0; j < 8; j++)
                    acc[i][j] = fmaf(a[i], b[j], acc[i][j]);
        }
        __syncthreads();
        buf ^= 1;
    }

#pragma unroll
    for (int i = 0; i < 8; i++) {
        int m = m0 + ty * 8 + i;
#pragma unroll
        for (int j = 0; j < 8; j += 4) {
            int n = n0 + tx * 8 + j;
            float4 v;
            v.x = acc[i][j + 0] + bi[n + 0];
            v.y = acc[i][j + 1] + bi[n + 1];
            v.z = acc[i][j + 2] + bi[n + 2];
            v.w = acc[i][j + 3] + bi[n + 3];
            *reinterpret_cast<float4*>(&g_ig[(size_t)m * G3 + n]) = v;
        }
    }
}

// ---------------- release / acquire helpers ----------------
__device__ __forceinline__ void flag_release(unsigned* p, unsigned v) {
    asm volatile("st.release.gpu.global.u32 [%0], %1;" :: "l"(p), "r"(v) : "memory");
}
__device__ __forceinline__ unsigned flag_acquire(const unsigned* p) {
    unsigned v;
    asm volatile("ld.acquire.gpu.global.u32 %0, [%1];" : "=r"(v) : "l"(p) : "memory");
    return v;
}

// =================================================================
// Kernel 2: persistent GRU scan (R6 structure — best measured).
//   148 CTAs x 256 threads, 1 CTA/SM.
//   Weights fully resident: 16 rows in registers + 26 rows in SMEM.
//   Grid sync: per-CTA epoch flags + block-wide rate-limited poll
//   (one ld.acquire round per __syncthreads_and). No threadfence:
//   bar.sync -> st.release -> ld.acquire chain provides visibility;
//   h lands at a fresh address every step (never stale in L1).
// =================================================================
#define NSR_MAX 26
#define SCAN_SMEM ((NSR_MAX * H + H + 64) * 4)   // 221,440 bytes

__global__ __launch_bounds__(256, 1)
void gru_scan(const float* __restrict__ Wh,
              const float* __restrict__ init_state,
              const float* __restrict__ bn,
              float* __restrict__ out)
{
    extern __shared__ float smem[];
    const int NB   = gridDim.x;
    const int cta  = blockIdx.x;
    const int tid  = threadIdx.x;
    const int lane = tid & 31;
    const int warp = tid >> 5;          // 0..7

    const int chunk = (H + NB - 1) / NB;
    const int j0    = cta * chunk;
    int nj = H - j0;
    if (nj > chunk) nj = chunk;
    if (nj < 0) nj = 0;
    const int nrows = 3 * nj;

    float* sw    = smem;                 // NSR_MAX rows x 2048 (rows 16..41)
    float* sh    = smem + NSR_MAX * H;   // staged h (2048)
    float* sdots = sh + H;               // 48 dot results
    float4* sh4  = reinterpret_cast<float4*>(sh);

    // epoch base: own flag (all flags equal at launch start)
    const unsigned epoch = g_flags[cta * 8];

    // ---- preload SMEM-resident weight rows (rr = 16..nrows-1), once ----
    const int nsr = (nrows > 16) ? (nrows - 16) : 0;   // <= 26
    for (int idx = tid; idx < nsr * (H / 4); idx += 256) {
        int r  = idx >> 9;
        int c  = idx & 511;
        int rr = 16 + r;
        int g  = rr / nj;
        int jj = rr - g * nj;
        reinterpret_cast<float4*>(sw)[r * (H / 4) + c] =
            reinterpret_cast<const float4*>(Wh + (size_t)(g * H + j0 + jj) * H)[c];
    }

    // ---- per-warp row slots ----
    const int rr0 = warp,      rr1 = warp + 8,  rr2 = warp + 16;
    const int rr3 = warp + 24, rr4 = warp + 32, rr5 = warp + 40;
    const bool v0 = rr0 < nrows, v1 = rr1 < nrows, v2 = rr2 < nrows;
    const bool v3 = rr3 < nrows, v4 = rr4 < nrows, v5 = rr5 < nrows;

    // ---- register-resident weights for slots 0,1 ----
    float4 wreg0[16], wreg1[16];
    {
        const float* row;
        int g, jj;
        g = v0 ? (rr0 / nj) : 0; jj = v0 ? (rr0 - g * nj) : 0;
        row = Wh + (size_t)(g * H + j0 + jj) * H;
#pragma unroll
        for (int i = 0; i < 16; i++)
            wreg0[i] = reinterpret_cast<const float4*>(row)[lane + 32 * i];
        g = v1 ? (rr1 / nj) : 0; jj = v1 ? (rr1 - g * nj) : 0;
        row = Wh + (size_t)(g * H + j0 + jj) * H;
#pragma unroll
        for (int i = 0; i < 16; i++)
            wreg1[i] = reinterpret_cast<const float4*>(row)[lane + 32 * i];
    }

    const float4* p2 = reinterpret_cast<const float4*>(v2 ? (sw + (rr2 - 16) * H) : sw);
    const float4* p3 = reinterpret_cast<const float4*>(v3 ? (sw + (rr3 - 16) * H) : sw);
    const float4* p4 = reinterpret_cast<const float4*>(v4 ? (sw + (rr4 - 16) * H) : sw);
    const float4* p5 = reinterpret_cast<const float4*>(v5 ? (sw + (rr5 - 16) * H) : sw);

    const bool doPoint = (tid < nj);
    const int  myj     = j0 + (doPoint ? tid : 0);
    const float mybn   = doPoint ? bn[myj] : 0.f;

    // prefetch igates for t = 0
    float gr = 0.f, gz = 0.f, gnv = 0.f;
    if (doPoint) {
        gr  = g_ig[myj];
        gz  = g_ig[H + myj];
        gnv = g_ig[2 * H + myj];
    }

    __syncthreads();   // SMEM weights ready

#pragma unroll 1
    for (int t = 0; t < T; t++) {
        // ---- stage h_{t-1} into SMEM (8 KB from L2) ----
        const float* hsrc = (t == 0) ? init_state : (out + (size_t)(t - 1) * H);
#pragma unroll
        for (int p = 0; p < 2; p++)
            sh4[tid + p * 256] = reinterpret_cast<const float4*>(hsrc)[tid + p * 256];
        __syncthreads();

        // ---- six dot products per warp ----
        float a0 = 0.f, a1 = 0.f, a2 = 0.f, a3 = 0.f, a4 = 0.f, a5 = 0.f;
#pragma unroll
        for (int i = 0; i < 16; i++) {
            const int k = lane + 32 * i;
            const float4 hv = sh4[k];
            a0 = fmaf(wreg0[i].x, hv.x, a0); a0 = fmaf(wreg0[i].y, hv.y, a0);
            a0 = fmaf(wreg0[i].z, hv.z, a0); a0 = fmaf(wreg0[i].w, hv.w, a0);
            a1 = fmaf(wreg1[i].x, hv.x, a1); a1 = fmaf(wreg1[i].y, hv.y, a1);
            a1 = fmaf(wreg1[i].z, hv.z, a1); a1 = fmaf(wreg1[i].w, hv.w, a1);
            if (v2) { float4 w = p2[k];
                a2 = fmaf(w.x, hv.x, a2); a2 = fmaf(w.y, hv.y, a2);
                a2 = fmaf(w.z, hv.z, a2); a2 = fmaf(w.w, hv.w, a2); }
            if (v3) { float4 w = p3[k];
                a3 = fmaf(w.x, hv.x, a3); a3 = fmaf(w.y, hv.y, a3);
                a3 = fmaf(w.z, hv.z, a3); a3 = fmaf(w.w, hv.w, a3); }
            if (v4) { float4 w = p4[k];
                a4 = fmaf(w.x, hv.x, a4); a4 = fmaf(w.y, hv.y, a4);
                a4 = fmaf(w.z, hv.z, a4); a4 = fmaf(w.w, hv.w, a4); }
            if (v5) { float4 w = p5[k];
                a5 = fmaf(w.x, hv.x, a5); a5 = fmaf(w.y, hv.y, a5);
                a5 = fmaf(w.z, hv.z, a5); a5 = fmaf(w.w, hv.w, a5); }
        }
#pragma unroll
        for (int off = 16; off; off >>= 1) {
            a0 += __shfl_xor_sync(0xffffffffu, a0, off);
            a1 += __shfl_xor_sync(0xffffffffu, a1, off);
            a2 += __shfl_xor_sync(0xffffffffu, a2, off);
            a3 += __shfl_xor_sync(0xffffffffu, a3, off);
            a4 += __shfl_xor_sync(0xffffffffu, a4, off);
            a5 += __shfl_xor_sync(0xffffffffu, a5, off);
        }
        if (lane == 0) {
            if (v0) sdots[rr0] = a0;
            if (v1) sdots[rr1] = a1;
            if (v2) sdots[rr2] = a2;
            if (v3) sdots[rr3] = a3;
            if (v4) sdots[rr4] = a4;
            if (v5) sdots[rr5] = a5;
        }
        __syncthreads();

        // ---- pointwise GRU update (fast transcendentals) ----
        if (doPoint) {
            float hr = sdots[tid];
            float hz = sdots[nj + tid];
            float hn = sdots[2 * nj + tid];
            float r  = __fdividef(1.f, 1.f + __expf(-(gr + hr)));
            float u  = __fdividef(1.f, 1.f + __expf(-(gz + hz)));
            float x  = gnv + r * (hn + mybn);
            float nv = __fdividef(2.f, 1.f + __expf(-2.f * x)) - 1.f;  // tanh
            float hprev = sh[myj];
            float hnext = (1.f - u) * nv + u * hprev;
            out[(size_t)t * H + myj] = hnext;
            if (t == T - 1) out[(size_t)T * H + myj] = hnext;  // last_state
        }

        // ---- grid barrier: post own flag, prefetch, block-wide poll ----
        const unsigned target = epoch + (unsigned)(t + 1);
        __syncthreads();                       // all h stores issued (CTA-ordered)
        if (tid == 0)
            flag_release(&g_flags[cta * 8], target);

        // overlap: issue next step's igate loads while barrier resolves
        if (doPoint && (t + 1) < T) {
            const float* igt = g_ig + (size_t)(t + 1) * G3;
            gr  = igt[myj];
            gz  = igt[H + myj];
            gnv = igt[2 * H + myj];
        }

        // rate-limited parallel flag check: one poll round per bar
        for (;;) {
            bool p = true;
            if (tid < NB)
                p = ((int)(flag_acquire(&g_flags[tid * 8]) - target) >= 0);
            if (__syncthreads_and(p)) break;
        }
    }
}

// =================================================================
// launch
// =================================================================
extern "C" void kernel_launch(void* const* d_in, const int* in_sizes, int n_in,
                              void* d_out, int out_size)
{
    const float* xs         = (const float*)d_in[0];  // [4096,2048]
    const float* init_state = (const float*)d_in[1];  // [2048]
    const float* Wi         = (const float*)d_in[2];  // [6144,2048]
    const float* Wh         = (const float*)d_in[3];  // [6144,2048]
    const float* bi         = (const float*)d_in[4];  // [6144]
    const float* bn         = (const float*)d_in[5];  // [2048]
    float* out              = (float*)d_out;          // [4096*2048 + 2048]

    (void)in_sizes; (void)n_in; (void)out_size;

    // 1) input-gate GEMM: grid (N/BN, M/BM) = (48, 32)
    igates_gemm<<<dim3(G3 / BN, T / BM), 256>>>(xs, Wi, bi);

    // 2) persistent scan: one CTA per SM
    int dev = 0;
    cudaGetDevice(&dev);
    int nsm = 148;
    cudaDeviceGetAttribute(&nsm, cudaDevAttrMultiProcessorCount, dev);
    if (nsm < 1) nsm = 148;
    if (nsm > NBMAX) nsm = NBMAX;

    cudaFuncSetAttribute(gru_scan, cudaFuncAttributeMaxDynamicSharedMemorySize, SCAN_SMEM);
    gru_scan<<<nsm, 256, SCAN_SMEM>>>(Wh, init_state, bn, out);
}

// round 11
// speedup vs baseline: 1.6388x; 1.0973x over previous
#include <cuda_runtime.h>
#include <math.h>

#define H     2048
#define T     4096
#define G3    (3 * H)
#define K_IN  2048
#define NBMAX 160
#define PKT   6          // packet slots per CTA (3 h-values per 16B packet)
#define PKTS  8          // float4 stride per CTA line (128B, padded)

// ---------------- device scratch ----------------
__device__ float    g_ig[(size_t)T * G3];                    // igates [T][3H]
__device__ float4   g_hp[(size_t)T * NBMAX * PKTS];          // h packets (~84 MB)
__device__ unsigned g_epochs[NBMAX * 8];                     // per-CTA epoch counters

// =================================================================
// Kernel 1: igates = xs @ Wi^T + bi
//   fp32 SMEM-tiled GEMM, double-buffered, conflict-free fragments
//   (4+4 split at +64 -> 16B lane stride LDS.128, no bank conflicts).
// =================================================================
#define BM 128
#define BN 128
#define BK 16

__global__ __launch_bounds__(256, 2)
void igates_gemm(const float* __restrict__ A,
                 const float* __restrict__ B,
                 const float* __restrict__ bi)
{
    __shared__ float As[2][BK][BM + 4];
    __shared__ float Bs[2][BK][BN + 4];

    const int tid = threadIdx.x;
    const int m0  = blockIdx.y * BM;
    const int n0  = blockIdx.x * BN;
    const int tx  = tid & 15;
    const int ty  = tid >> 4;

    const int r0 = tid >> 1;               // 0..127
    const int c0 = (tid & 1) * 8;          // 0 or 8

    float acc[8][8];
#pragma unroll
    for (int i = 0; i < 8; i++)
#pragma unroll
        for (int j = 0; j < 8; j++) acc[i][j] = 0.f;

    // prologue fetch
    float4 ra0, ra1, rb0, rb1;
    ra0 = *reinterpret_cast<const float4*>(&A[(size_t)(m0 + r0) * K_IN + c0]);
    ra1 = *reinterpret_cast<const float4*>(&A[(size_t)(m0 + r0) * K_IN + c0 + 4]);
    rb0 = *reinterpret_cast<const float4*>(&B[(size_t)(n0 + r0) * K_IN + c0]);
    rb1 = *reinterpret_cast<const float4*>(&B[(size_t)(n0 + r0) * K_IN + c0 + 4]);

    int buf = 0;
    for (int k0 = 0; k0 < K_IN; k0 += BK) {
        As[buf][c0 + 0][r0] = ra0.x; As[buf][c0 + 1][r0] = ra0.y;
        As[buf][c0 + 2][r0] = ra0.z; As[buf][c0 + 3][r0] = ra0.w;
        As[buf][c0 + 4][r0] = ra1.x; As[buf][c0 + 5][r0] = ra1.y;
        As[buf][c0 + 6][r0] = ra1.z; As[buf][c0 + 7][r0] = ra1.w;
        Bs[buf][c0 + 0][r0] = rb0.x; Bs[buf][c0 + 1][r0] = rb0.y;
        Bs[buf][c0 + 2][r0] = rb0.z; Bs[buf][c0 + 3][r0] = rb0.w;
        Bs[buf][c0 + 4][r0] = rb1.x; Bs[buf][c0 + 5][r0] = rb1.y;
        Bs[buf][c0 + 6][r0] = rb1.z; Bs[buf][c0 + 7][r0] = rb1.w;
        __syncthreads();

        if (k0 + BK < K_IN) {
            const int kn = k0 + BK;
            ra0 = *reinterpret_cast<const float4*>(&A[(size_t)(m0 + r0) * K_IN + kn + c0]);
            ra1 = *reinterpret_cast<const float4*>(&A[(size_t)(m0 + r0) * K_IN + kn + c0 + 4]);
            rb0 = *reinterpret_cast<const float4*>(&B[(size_t)(n0 + r0) * K_IN + kn + c0]);
            rb1 = *reinterpret_cast<const float4*>(&B[(size_t)(n0 + r0) * K_IN + kn + c0 + 4]);
        }

#pragma unroll
        for (int kk = 0; kk < BK; kk++) {
            float a[8], b[8];
            *reinterpret_cast<float4*>(&a[0]) = *reinterpret_cast<float4*>(&As[buf][kk][ty * 4]);
            *reinterpret_cast<float4*>(&a[4]) = *reinterpret_cast<float4*>(&As[buf][kk][ty * 4 + 64]);
            *reinterpret_cast<float4*>(&b[0]) = *reinterpret_cast<float4*>(&Bs[buf][kk][tx * 4]);
            *reinterpret_cast<float4*>(&b[4]) = *reinterpret_cast<float4*>(&Bs[buf][kk][tx * 4 + 64]);
#pragma unroll
            for (int i = 0; i < 8; i++)
#pragma unroll
                for (int j = 0; j < 8; j++)
                    acc[i][j] = fmaf(a[i], b[j], acc[i][j]);
        }
        __syncthreads();
        buf ^= 1;
    }

    // epilogue: rows m0+ty*4+{0..3} and m0+64+ty*4+{0..3};
    //           cols n0+tx*4+{0..3} and n0+64+tx*4+{0..3}
#pragma unroll
    for (int i = 0; i < 8; i++) {
        int m = (i < 4) ? (m0 + ty * 4 + i) : (m0 + 64 + ty * 4 + i - 4);
        int nA = n0 + tx * 4;
        int nB = n0 + 64 + tx * 4;
        float4 v0, v1;
        v0.x = acc[i][0] + bi[nA + 0];
        v0.y = acc[i][1] + bi[nA + 1];
        v0.z = acc[i][2] + bi[nA + 2];
        v0.w = acc[i][3] + bi[nA + 3];
        v1.x = acc[i][4] + bi[nB + 0];
        v1.y = acc[i][5] + bi[nB + 1];
        v1.z = acc[i][6] + bi[nB + 2];
        v1.w = acc[i][7] + bi[nB + 3];
        *reinterpret_cast<float4*>(&g_ig[(size_t)m * G3 + nA]) = v0;
        *reinterpret_cast<float4*>(&g_ig[(size_t)m * G3 + nB]) = v1;
    }
}

// =================================================================
// Kernel 2: persistent GRU scan with TAGGED-PACKET h exchange.
//   148 CTAs x 256 threads, 1 CTA/SM.
//   Weights fully resident: 16 rows in registers + 26 rows in SMEM.
//   Exchange: producer publishes h as 16B packets {h0,h1,h2,tag}
//   (one stcg each — payload+tag in one 128-bit transaction).
//   Consumers ldcg packets, check embedded tags, advance via
//   syncthreads_and (rate-limited poll). One L2 round trip delivers
//   flag AND data.
// =================================================================
#define NSR_MAX 26
#define SCAN_SMEM ((NSR_MAX * H + H + 96) * 4)

__global__ __launch_bounds__(256, 1)
void gru_scan(const float* __restrict__ Wh,
              const float* __restrict__ init_state,
              const float* __restrict__ bn,
              float* __restrict__ out)
{
    extern __shared__ float smem[];
    const int NB   = gridDim.x;
    const int cta  = blockIdx.x;
    const int tid  = threadIdx.x;
    const int lane = tid & 31;
    const int warp = tid >> 5;          // 0..7

    const int chunk = (H + NB - 1) / NB;     // 14 at NB=148
    const int j0    = cta * chunk;
    int nj = H - j0;
    if (nj > chunk) nj = chunk;
    if (nj < 0) nj = 0;
    const int nrows = 3 * nj;

    float* sw    = smem;                 // NSR_MAX rows x 2048 (rows 16..41)
    float* sh    = smem + NSR_MAX * H;   // staged h (2048)
    float* sdots = sh + H;               // 48 dot results
    float* shn   = sdots + 48;           // this CTA's h_next (<=18)
    float4* sh4  = reinterpret_cast<float4*>(sh);

    const unsigned epoch = g_epochs[cta * 8];

    // ---- preload SMEM-resident weight rows (rr = 16..nrows-1), once ----
    const int nsr = (nrows > 16) ? (nrows - 16) : 0;   // <= 26
    for (int idx = tid; idx < nsr * (H / 4); idx += 256) {
        int r  = idx >> 9;
        int c  = idx & 511;
        int rr = 16 + r;
        int g  = rr / nj;
        int jj = rr - g * nj;
        reinterpret_cast<float4*>(sw)[r * (H / 4) + c] =
            reinterpret_cast<const float4*>(Wh + (size_t)(g * H + j0 + jj) * H)[c];
    }

    // ---- per-warp row slots ----
    const int rr0 = warp,      rr1 = warp + 8,  rr2 = warp + 16;
    const int rr3 = warp + 24, rr4 = warp + 32, rr5 = warp + 40;
    const bool v0 = rr0 < nrows, v1 = rr1 < nrows, v2 = rr2 < nrows;
    const bool v3 = rr3 < nrows, v4 = rr4 < nrows, v5 = rr5 < nrows;

    // ---- register-resident weights for slots 0,1 ----
    float4 wreg0[16], wreg1[16];
    {
        const float* row;
        int g, jj;
        g = v0 ? (rr0 / nj) : 0; jj = v0 ? (rr0 - g * nj) : 0;
        row = Wh + (size_t)(g * H + j0 + jj) * H;
#pragma unroll
        for (int i = 0; i < 16; i++)
            wreg0[i] = reinterpret_cast<const float4*>(row)[lane + 32 * i];
        g = v1 ? (rr1 / nj) : 0; jj = v1 ? (rr1 - g * nj) : 0;
        row = Wh + (size_t)(g * H + j0 + jj) * H;
#pragma unroll
        for (int i = 0; i < 16; i++)
            wreg1[i] = reinterpret_cast<const float4*>(row)[lane + 32 * i];
    }

    const float4* p2 = reinterpret_cast<const float4*>(v2 ? (sw + (rr2 - 16) * H) : sw);
    const float4* p3 = reinterpret_cast<const float4*>(v3 ? (sw + (rr3 - 16) * H) : sw);
    const float4* p4 = reinterpret_cast<const float4*>(v4 ? (sw + (rr4 - 16) * H) : sw);
    const float4* p5 = reinterpret_cast<const float4*>(v5 ? (sw + (rr5 - 16) * H) : sw);

    const bool doPoint = (tid < nj);
    const int  myj     = j0 + (doPoint ? tid : 0);
    const float mybn   = doPoint ? bn[myj] : 0.f;

    // ---- consumer packet assignment: thread handles pkts tid+256*k ----
    int  pline[4], pdst[4], pcnt[4];
    bool pact[4];
#pragma unroll
    for (int k = 0; k < 4; k++) {
        int g = tid + 256 * k;
        bool have = (g < NB * PKT);
        int c = have ? (g / PKT) : 0;
        int p = have ? (g % PKT) : 0;
        int cnj = H - c * chunk;
        if (cnj > chunk) cnj = chunk;
        if (cnj < 0) cnj = 0;
        int cnt = cnj - 3 * p;
        if (cnt > 3) cnt = 3;
        pact[k]  = have && (cnt > 0);
        pcnt[k]  = (cnt > 0) ? cnt : 0;
        pline[k] = c * PKTS + p;
        pdst[k]  = c * chunk + 3 * p;
    }

    // prefetch igates for t = 0
    float gr = 0.f, gz = 0.f, gnv = 0.f;
    if (doPoint) {
        gr  = g_ig[myj];
        gz  = g_ig[H + myj];
        gnv = g_ig[2 * H + myj];
    }

    __syncthreads();   // SMEM weights ready

#pragma unroll 1
    for (int t = 0; t < T; t++) {
        // ---- acquire h_{t-1} ----
        if (t == 0) {
            sh4[tid]       = reinterpret_cast<const float4*>(init_state)[tid];
            sh4[tid + 256] = reinterpret_cast<const float4*>(init_state)[tid + 256];
            __syncthreads();
        } else {
            const unsigned target = epoch + (unsigned)t;   // producers posted epoch+t
            const float4* base = g_hp + (size_t)(t - 1) * NBMAX * PKTS;
            float4 d0, d1, d2, d3;
            bool ok0 = !pact[0], ok1 = !pact[1], ok2 = !pact[2], ok3 = !pact[3];
            for (;;) {
                if (!ok0) { d0 = __ldcg(base + pline[0]);
                            ok0 = ((int)(__float_as_uint(d0.w) - target) >= 0); }
                if (!ok1) { d1 = __ldcg(base + pline[1]);
                            ok1 = ((int)(__float_as_uint(d1.w) - target) >= 0); }
                if (!ok2) { d2 = __ldcg(base + pline[2]);
                            ok2 = ((int)(__float_as_uint(d2.w) - target) >= 0); }
                if (!ok3) { d3 = __ldcg(base + pline[3]);
                            ok3 = ((int)(__float_as_uint(d3.w) - target) >= 0); }
                if (__syncthreads_and(ok0 && ok1 && ok2 && ok3)) break;
            }
            // scatter payloads into sh
            if (pact[0]) { sh[pdst[0]] = d0.x;
                           if (pcnt[0] > 1) sh[pdst[0] + 1] = d0.y;
                           if (pcnt[0] > 2) sh[pdst[0] + 2] = d0.z; }
            if (pact[1]) { sh[pdst[1]] = d1.x;
                           if (pcnt[1] > 1) sh[pdst[1] + 1] = d1.y;
                           if (pcnt[1] > 2) sh[pdst[1] + 2] = d1.z; }
            if (pact[2]) { sh[pdst[2]] = d2.x;
                           if (pcnt[2] > 1) sh[pdst[2] + 1] = d2.y;
                           if (pcnt[2] > 2) sh[pdst[2] + 2] = d2.z; }
            if (pact[3]) { sh[pdst[3]] = d3.x;
                           if (pcnt[3] > 1) sh[pdst[3] + 1] = d3.y;
                           if (pcnt[3] > 2) sh[pdst[3] + 2] = d3.z; }
            __syncthreads();
        }

        // ---- six dot products per warp ----
        float a0 = 0.f, a1 = 0.f, a2 = 0.f, a3 = 0.f, a4 = 0.f, a5 = 0.f;
#pragma unroll
        for (int i = 0; i < 16; i++) {
            const int k = lane + 32 * i;
            const float4 hv = sh4[k];
            a0 = fmaf(wreg0[i].x, hv.x, a0); a0 = fmaf(wreg0[i].y, hv.y, a0);
            a0 = fmaf(wreg0[i].z, hv.z, a0); a0 = fmaf(wreg0[i].w, hv.w, a0);
            a1 = fmaf(wreg1[i].x, hv.x, a1); a1 = fmaf(wreg1[i].y, hv.y, a1);
            a1 = fmaf(wreg1[i].z, hv.z, a1); a1 = fmaf(wreg1[i].w, hv.w, a1);
            if (v2) { float4 w = p2[k];
                a2 = fmaf(w.x, hv.x, a2); a2 = fmaf(w.y, hv.y, a2);
                a2 = fmaf(w.z, hv.z, a2); a2 = fmaf(w.w, hv.w, a2); }
            if (v3) { float4 w = p3[k];
                a3 = fmaf(w.x, hv.x, a3); a3 = fmaf(w.y, hv.y, a3);
                a3 = fmaf(w.z, hv.z, a3); a3 = fmaf(w.w, hv.w, a3); }
            if (v4) { float4 w = p4[k];
                a4 = fmaf(w.x, hv.x, a4); a4 = fmaf(w.y, hv.y, a4);
                a4 = fmaf(w.z, hv.z, a4); a4 = fmaf(w.w, hv.w, a4); }
            if (v5) { float4 w = p5[k];
                a5 = fmaf(w.x, hv.x, a5); a5 = fmaf(w.y, hv.y, a5);
                a5 = fmaf(w.z, hv.z, a5); a5 = fmaf(w.w, hv.w, a5); }
        }
#pragma unroll
        for (int off = 16; off; off >>= 1) {
            a0 += __shfl_xor_sync(0xffffffffu, a0, off);
            a1 += __shfl_xor_sync(0xffffffffu, a1, off);
            a2 += __shfl_xor_sync(0xffffffffu, a2, off);
            a3 += __shfl_xor_sync(0xffffffffu, a3, off);
            a4 += __shfl_xor_sync(0xffffffffu, a4, off);
            a5 += __shfl_xor_sync(0xffffffffu, a5, off);
        }
        if (lane == 0) {
            if (v0) sdots[rr0] = a0;
            if (v1) sdots[rr1] = a1;
            if (v2) sdots[rr2] = a2;
            if (v3) sdots[rr3] = a3;
            if (v4) sdots[rr4] = a4;
            if (v5) sdots[rr5] = a5;
        }
        __syncthreads();

        // ---- pointwise GRU update ----
        if (doPoint) {
            float hr = sdots[tid];
            float hz = sdots[nj + tid];
            float hn = sdots[2 * nj + tid];
            float r  = __fdividef(1.f, 1.f + __expf(-(gr + hr)));
            float u  = __fdividef(1.f, 1.f + __expf(-(gz + hz)));
            float x  = gnv + r * (hn + mybn);
            float nv = __fdividef(2.f, 1.f + __expf(-2.f * x)) - 1.f;  // tanh
            float hprev = sh[myj];
            float hnext = (1.f - u) * nv + u * hprev;
            shn[tid] = hnext;                                   // for packets
            out[(size_t)t * H + myj] = hnext;                   // output (write-only)
            if (t == T - 1) out[(size_t)T * H + myj] = hnext;   // last_state
        }
        __syncthreads();   // shn visible to packet assemblers

        // ---- publish packets: {h0,h1,h2,tag} in ONE 16B store each ----
        if (tid < PKT) {
            int b = 3 * tid;
            if (b < nj) {
                float4 v;
                v.x = shn[b];
                v.y = (b + 1 < nj) ? shn[b + 1] : 0.f;
                v.z = (b + 2 < nj) ? shn[b + 2] : 0.f;
                v.w = __uint_as_float(epoch + (unsigned)(t + 1));
                __stcg(g_hp + ((size_t)t * NBMAX + cta) * PKTS + tid, v);
            }
        }

        // overlap: next step's igate loads fly during upcoming polls
        if (doPoint && (t + 1) < T) {
            const float* igt = g_ig + (size_t)(t + 1) * G3;
            gr  = igt[myj];
            gz  = igt[H + myj];
            gnv = igt[2 * H + myj];
        }
    }

    if (tid == 0)
        g_epochs[cta * 8] = epoch + (unsigned)T;
}

// =================================================================
// launch
// =================================================================
extern "C" void kernel_launch(void* const* d_in, const int* in_sizes, int n_in,
                              void* d_out, int out_size)
{
    const float* xs         = (const float*)d_in[0];  // [4096,2048]
    const float* init_state = (const float*)d_in[1];  // [2048]
    const float* Wi         = (const float*)d_in[2];  // [6144,2048]
    const float* Wh         = (const float*)d_in[3];  // [6144,2048]
    const float* bi         = (const float*)d_in[4];  // [6144]
    const float* bn         = (const float*)d_in[5];  // [2048]
    float* out              = (float*)d_out;          // [4096*2048 + 2048]

    (void)in_sizes; (void)n_in; (void)out_size;

    // 1) input-gate GEMM: grid (N/BN, M/BM) = (48, 32)
    igates_gemm<<<dim3(G3 / BN, T / BM), 256>>>(xs, Wi, bi);

    // 2) persistent scan: one CTA per SM
    int dev = 0;
    cudaGetDevice(&dev);
    int nsm = 148;
    cudaDeviceGetAttribute(&nsm, cudaDevAttrMultiProcessorCount, dev);
    if (nsm < 1) nsm = 148;
    if (nsm > NBMAX) nsm = NBMAX;

    cudaFuncSetAttribute(gru_scan, cudaFuncAttributeMaxDynamicSharedMemorySize, SCAN_SMEM);
    gru_scan<<<nsm, 256, SCAN_SMEM>>>(Wh, init_state, bn, out);
}